// round 2
// baseline (speedup 1.0000x reference)
#include <cuda_runtime.h>
#include <math.h>

#define N_NODES 80000
#define N_EDGES 1280000
#define IN_C    128
#define HID_C   64
#define OUT_C   40

#define SCAN_CHUNK 1024
#define NCHUNK ((N_NODES + SCAN_CHUNK - 1) / SCAN_CHUNK)   // 79

// ---------------- static device scratch (no allocations allowed) ----------
__device__ float g_h1[N_NODES * HID_C];     // x @ W1
__device__ float g_h2[N_NODES * OUT_C];     // relu(agg(h1)) @ W2
__device__ int   g_deg[N_NODES];
__device__ int   g_off[N_NODES + 1];
__device__ int   g_cur[N_NODES];
__device__ int   g_csr_src[N_EDGES];
__device__ unsigned long long g_pack[NCHUNK];  // lookback: (flag<<32)|value

// ============ K1: GEMM1 (h1 = x @ W1) + zero deg + reset scan state =======

__global__ __launch_bounds__(256) void k_gemm1_zero(const float* __restrict__ x,
                                                    const float* __restrict__ W1) {
    __shared__ float Ws[IN_C * HID_C];   // 32 KB
    for (int i = threadIdx.x; i < IN_C * HID_C; i += blockDim.x) Ws[i] = W1[i];

    int v = blockIdx.x * blockDim.x + threadIdx.x;
    if (v < N_NODES) g_deg[v] = 0;
    if (blockIdx.x == 0 && threadIdx.x < NCHUNK) g_pack[threadIdx.x] = 0ull;
    __syncthreads();

    if (v >= N_NODES) return;

    float acc[HID_C];
#pragma unroll
    for (int j = 0; j < HID_C; j++) acc[j] = 0.f;

    const float4* xr = (const float4*)(x + (size_t)v * IN_C);
#pragma unroll 2
    for (int k4 = 0; k4 < IN_C / 4; k4++) {
        float4 xv = xr[k4];
        int kb = k4 * 4;
#pragma unroll
        for (int c = 0; c < 4; c++) {
            float xc = (c == 0) ? xv.x : (c == 1) ? xv.y : (c == 2) ? xv.z : xv.w;
            const float4* wr = (const float4*)(Ws + (kb + c) * HID_C);
#pragma unroll
            for (int j4 = 0; j4 < HID_C / 4; j4++) {
                float4 w = wr[j4];
                acc[4 * j4 + 0] += xc * w.x;
                acc[4 * j4 + 1] += xc * w.y;
                acc[4 * j4 + 2] += xc * w.z;
                acc[4 * j4 + 3] += xc * w.w;
            }
        }
    }
    float4* o = (float4*)(g_h1 + (size_t)v * HID_C);
#pragma unroll
    for (int j4 = 0; j4 < HID_C / 4; j4++)
        o[j4] = make_float4(acc[4*j4], acc[4*j4+1], acc[4*j4+2], acc[4*j4+3]);
}

// ============ K2: degree histogram (int4 vectorized) ======================

__global__ void k_hist(const int* __restrict__ ei) {
    int t = blockIdx.x * blockDim.x + threadIdx.x;
    if (t < N_EDGES / 4) {
        int4 d = ((const int4*)(ei + N_EDGES))[t];
        atomicAdd(&g_deg[d.x], 1);
        atomicAdd(&g_deg[d.y], 1);
        atomicAdd(&g_deg[d.z], 1);
        atomicAdd(&g_deg[d.w], 1);
    }
}

// ============ K3: single-kernel exclusive scan w/ decoupled lookback ======

__device__ __forceinline__ int block_scan_excl(int v, int* smem32) {
    int lane = threadIdx.x & 31;
    int wid  = threadIdx.x >> 5;
    int nw   = blockDim.x >> 5;
    int s = v;
#pragma unroll
    for (int d = 1; d < 32; d <<= 1) {
        int t = __shfl_up_sync(0xffffffffu, s, d);
        if (lane >= d) s += t;
    }
    if (lane == 31) smem32[wid] = s;
    __syncthreads();
    if (wid == 0) {
        int ws = (lane < nw) ? smem32[lane] : 0;
        int ss = ws;
#pragma unroll
        for (int d = 1; d < 32; d <<= 1) {
            int t = __shfl_up_sync(0xffffffffu, ss, d);
            if (lane >= d) ss += t;
        }
        smem32[lane] = ss - ws;
    }
    __syncthreads();
    return smem32[wid] + (s - v);
}

__global__ __launch_bounds__(SCAN_CHUNK) void k_scan() {   // NCHUNK blocks
    __shared__ int sm[32];
    __shared__ int s_total;
    __shared__ int s_base;

    int b = blockIdx.x;
    int i = b * SCAN_CHUNK + threadIdx.x;
    int v = (i < N_NODES) ? g_deg[i] : 0;
    int ex = block_scan_excl(v, sm);
    if (threadIdx.x == SCAN_CHUNK - 1) s_total = ex + v;
    __syncthreads();
    int total = s_total;

    // warp 0: decoupled lookback (packed 64-bit value|flag, no fence dance)
    if (threadIdx.x < 32) {
        int lane = threadIdx.x;
        int base = 0;
        if (b == 0) {
            if (lane == 0) {
                __threadfence();
                atomicExch(&g_pack[0], (2ull << 32) | (unsigned)total);
            }
        } else {
            // publish aggregate first
            if (lane == 0) {
                __threadfence();
                atomicExch(&g_pack[b], (1ull << 32) | (unsigned)total);
            }
            int p = b - 1;
            bool done = false;
            while (!done) {
                int idx = p - lane;
                unsigned long long w = 0;
                if (idx >= 0) {
                    do { w = atomicAdd(&g_pack[idx], 0ull); } while ((w >> 32) == 0);
                }
                int f = (int)(w >> 32);
                int val = (int)(w & 0xffffffffu);
                unsigned pm = __ballot_sync(0xffffffffu, idx >= 0 && f == 2);
                int cut;
                if (pm) { cut = __ffs(pm) - 1; done = true; }
                else    { cut = (p >= 31) ? 31 : p; }
                int contrib = (lane <= cut && idx >= 0) ? val : 0;
#pragma unroll
                for (int d = 16; d > 0; d >>= 1)
                    contrib += __shfl_xor_sync(0xffffffffu, contrib, d);
                base += contrib;
                p -= 32;
                if (p < 0) done = true;
            }
            if (lane == 0) {
                __threadfence();
                atomicExch(&g_pack[b], (2ull << 32) | (unsigned)(base + total));
                s_base = base;
            }
        }
        if (lane == 0 && b == 0) s_base = 0;
    }
    __syncthreads();
    int base = s_base;
    if (i < N_NODES) {
        g_off[i] = base + ex;
        g_cur[i] = base + ex;
    }
    if (b == NCHUNK - 1 && threadIdx.x == 0) g_off[N_NODES] = N_EDGES;
}

// ============ K4: CSR fill (int4 vectorized) ==============================

__global__ void k_fill(const int* __restrict__ ei) {
    int t = blockIdx.x * blockDim.x + threadIdx.x;
    if (t < N_EDGES / 4) {
        int4 s = ((const int4*)ei)[t];
        int4 d = ((const int4*)(ei + N_EDGES))[t];
        g_csr_src[atomicAdd(&g_cur[d.x], 1)] = s.x;
        g_csr_src[atomicAdd(&g_cur[d.y], 1)] = s.y;
        g_csr_src[atomicAdd(&g_cur[d.z], 1)] = s.z;
        g_csr_src[atomicAdd(&g_cur[d.w], 1)] = s.w;
    }
}

// ============ K5: fused SpMM1 + relu + GEMM2 ==============================
// warp per node: gather-sum h1 neighbors (float2/lane), relu -> smem,
// then 20 lanes compute 2 output cols each of h2 = a1 @ W2.

__global__ __launch_bounds__(256) void k_spmm1_gemm2(const float* __restrict__ W2) {
    __shared__ float W2s[HID_C * OUT_C];        // 10.25 KB
    __shared__ float a1s[8][HID_C];             // 2 KB
    for (int i = threadIdx.x; i < HID_C * OUT_C; i += blockDim.x) W2s[i] = W2[i];
    __syncthreads();

    int w = threadIdx.x >> 5;
    int lane = threadIdx.x & 31;
    int gw = blockIdx.x * 8 + w;
    if (gw >= N_NODES) return;

    int beg = g_off[gw], end = g_off[gw + 1];
    const float2* h1v = (const float2*)g_h1;

    float2 acc = make_float2(0.f, 0.f);
    int idx = beg;
    // full 32-edge chunks: one coalesced index load, broadcast via shuffle
    for (; idx + 32 <= end; idx += 32) {
        int s = __ldg(&g_csr_src[idx + lane]);
#pragma unroll
        for (int i = 0; i < 32; i++) {
            int si = __shfl_sync(0xffffffffu, s, i);
            float2 hv = __ldg(&h1v[(size_t)si * 32 + lane]);
            acc.x += hv.x; acc.y += hv.y;
        }
    }
    int rem = end - idx;
    if (rem > 0) {
        int s = (lane < rem) ? __ldg(&g_csr_src[idx + lane]) : 0;
#pragma unroll 4
        for (int i = 0; i < rem; i++) {
            int si = __shfl_sync(0xffffffffu, s, i);
            float2 hv = __ldg(&h1v[(size_t)si * 32 + lane]);
            acc.x += hv.x; acc.y += hv.y;
        }
    }
    // relu -> smem
    ((float2*)a1s[w])[lane] = make_float2(fmaxf(acc.x, 0.f), fmaxf(acc.y, 0.f));
    __syncwarp();

    // gemm: lanes 0..19 -> cols (2*lane, 2*lane+1)
    if (lane < OUT_C / 2) {
        float o0 = 0.f, o1 = 0.f;
        const float* a = a1s[w];
#pragma unroll
        for (int k = 0; k < HID_C; k++) {
            float av = a[k];                      // smem broadcast
            float2 wv = *(const float2*)(W2s + k * OUT_C + 2 * lane);
            o0 += av * wv.x;
            o1 += av * wv.y;
        }
        ((float2*)g_h2)[(size_t)gw * (OUT_C / 2) + lane] = make_float2(o0, o1);
    }
}

// ============ K6: SpMM2 + log_softmax =====================================

__global__ __launch_bounds__(256) void k_spmm2_lsm(float* __restrict__ out) {
    int w = threadIdx.x >> 5;
    int lane = threadIdx.x & 31;
    int gw = blockIdx.x * 8 + w;
    if (gw >= N_NODES) return;

    int beg = g_off[gw], end = g_off[gw + 1];
    const float2* h2v = (const float2*)g_h2;
    bool active = lane < (OUT_C / 2);

    float2 acc = make_float2(0.f, 0.f);
    int idx = beg;
    for (; idx + 32 <= end; idx += 32) {
        int s = __ldg(&g_csr_src[idx + lane]);
#pragma unroll
        for (int i = 0; i < 32; i++) {
            int si = __shfl_sync(0xffffffffu, s, i);
            if (active) {
                float2 hv = __ldg(&h2v[(size_t)si * (OUT_C / 2) + lane]);
                acc.x += hv.x; acc.y += hv.y;
            }
        }
    }
    int rem = end - idx;
    if (rem > 0) {
        int s = (lane < rem) ? __ldg(&g_csr_src[idx + lane]) : 0;
#pragma unroll 4
        for (int i = 0; i < rem; i++) {
            int si = __shfl_sync(0xffffffffu, s, i);
            if (active) {
                float2 hv = __ldg(&h2v[(size_t)si * (OUT_C / 2) + lane]);
                acc.x += hv.x; acc.y += hv.y;
            }
        }
    }

    float m = active ? fmaxf(acc.x, acc.y) : -INFINITY;
#pragma unroll
    for (int d = 16; d > 0; d >>= 1) m = fmaxf(m, __shfl_xor_sync(0xffffffffu, m, d));
    float sum = active ? (expf(acc.x - m) + expf(acc.y - m)) : 0.f;
#pragma unroll
    for (int d = 16; d > 0; d >>= 1) sum += __shfl_xor_sync(0xffffffffu, sum, d);
    float lse = logf(sum);
    if (active) {
        ((float2*)out)[(size_t)gw * (OUT_C / 2) + lane] =
            make_float2(acc.x - m - lse, acc.y - m - lse);
    }
}

// ---------------- launch ---------------------------------------------------

extern "C" void kernel_launch(void* const* d_in, const int* in_sizes, int n_in,
                              void* d_out, int out_size) {
    const float* x  = (const float*)d_in[0];     // [80000,128]
    const int*   ei = (const int*)d_in[1];       // [2,1280000]
    const float* W1 = (const float*)d_in[2];     // [128,64]
    const float* W2 = (const float*)d_in[3];     // [64,40]
    float* out = (float*)d_out;                  // [80000,40]

    const int TB = 256;

    k_gemm1_zero<<<(N_NODES + TB - 1) / TB, TB>>>(x, W1);       // also zeros deg + scan state
    k_hist<<<(N_EDGES / 4 + TB - 1) / TB, TB>>>(ei);
    k_scan<<<NCHUNK, SCAN_CHUNK>>>();
    k_fill<<<(N_EDGES / 4 + TB - 1) / TB, TB>>>(ei);
    k_spmm1_gemm2<<<(N_NODES + 7) / 8, TB>>>(W2);
    k_spmm2_lsm<<<(N_NODES + 7) / 8, TB>>>(out);
}

// round 4
// speedup vs baseline: 1.0213x; 1.0213x over previous
#include <cuda_runtime.h>
#include <math.h>

#define N_NODES 80000
#define N_EDGES 1280000
#define IN_C    128
#define HID_C   64
#define OUT_C   40

#define SCAN_CHUNK 1024
#define NCHUNK ((N_NODES + SCAN_CHUNK - 1) / SCAN_CHUNK)   // 79

typedef unsigned long long u64;

// ---------------- static device scratch (no allocations allowed) ----------
__device__ float g_h1[N_NODES * HID_C];     // x @ W1
__device__ float g_h2[N_NODES * OUT_C];     // relu(agg(h1)) @ W2
__device__ int   g_deg[N_NODES];
__device__ int   g_off[N_NODES + 1];
__device__ int   g_cur[N_NODES];
__device__ int   g_csr_src[N_EDGES];
__device__ u64   g_pack[NCHUNK];            // lookback: (flag<<32)|value

// packed fp32x2 helpers (Blackwell FFMA2 — ptxas never emits from C++)
__device__ __forceinline__ void fma2(u64& d, u64 a, u64 b) {
    asm("fma.rn.f32x2 %0, %1, %2, %0;" : "+l"(d) : "l"(a), "l"(b));
}
__device__ __forceinline__ u64 pack2(float x) {
    u64 r; asm("mov.b64 %0, {%1, %1};" : "=l"(r) : "f"(x)); return r;
}

// ============ K1: GEMM1 (h1 = x @ W1) + zero deg + reset scan state =======

__global__ __launch_bounds__(256) void k_gemm1_zero(const float* __restrict__ x,
                                                    const float* __restrict__ W1) {
    __shared__ float Ws[IN_C * HID_C];   // 32 KB
    for (int i = threadIdx.x; i < IN_C * HID_C; i += blockDim.x) Ws[i] = W1[i];

    int v = blockIdx.x * blockDim.x + threadIdx.x;
    if (v < N_NODES) g_deg[v] = 0;
    if (blockIdx.x == 0 && threadIdx.x < NCHUNK) g_pack[threadIdx.x] = 0ull;
    __syncthreads();

    if (v >= N_NODES) return;

    u64 acc[HID_C / 2];
#pragma unroll
    for (int j = 0; j < HID_C / 2; j++) acc[j] = 0ull;   // two packed +0.0f

    const float4* xr = (const float4*)(x + (size_t)v * IN_C);
#pragma unroll 2
    for (int k4 = 0; k4 < IN_C / 4; k4++) {
        float4 xv = xr[k4];
        int kb = k4 * 4;
#pragma unroll
        for (int c = 0; c < 4; c++) {
            float xc = (c == 0) ? xv.x : (c == 1) ? xv.y : (c == 2) ? xv.z : xv.w;
            u64 x2 = pack2(xc);
            const u64* wr = (const u64*)(Ws + (kb + c) * HID_C);
#pragma unroll
            for (int j = 0; j < HID_C / 2; j++)
                fma2(acc[j], x2, wr[j]);
        }
    }
    u64* o = (u64*)(g_h1 + (size_t)v * HID_C);
#pragma unroll
    for (int j = 0; j < HID_C / 2; j++) o[j] = acc[j];
}

// ============ K2: degree histogram (int4 vectorized) ======================

__global__ void k_hist(const int* __restrict__ ei) {
    int t = blockIdx.x * blockDim.x + threadIdx.x;
    if (t < N_EDGES / 4) {
        int4 d = ((const int4*)(ei + N_EDGES))[t];
        atomicAdd(&g_deg[d.x], 1);
        atomicAdd(&g_deg[d.y], 1);
        atomicAdd(&g_deg[d.z], 1);
        atomicAdd(&g_deg[d.w], 1);
    }
}

// ============ K3: single-kernel exclusive scan w/ decoupled lookback ======

__device__ __forceinline__ int block_scan_excl(int v, int* smem32) {
    int lane = threadIdx.x & 31;
    int wid  = threadIdx.x >> 5;
    int nw   = blockDim.x >> 5;
    int s = v;
#pragma unroll
    for (int d = 1; d < 32; d <<= 1) {
        int t = __shfl_up_sync(0xffffffffu, s, d);
        if (lane >= d) s += t;
    }
    if (lane == 31) smem32[wid] = s;
    __syncthreads();
    if (wid == 0) {
        int ws = (lane < nw) ? smem32[lane] : 0;
        int ss = ws;
#pragma unroll
        for (int d = 1; d < 32; d <<= 1) {
            int t = __shfl_up_sync(0xffffffffu, ss, d);
            if (lane >= d) ss += t;
        }
        smem32[lane] = ss - ws;
    }
    __syncthreads();
    return smem32[wid] + (s - v);
}

__global__ __launch_bounds__(SCAN_CHUNK) void k_scan() {   // NCHUNK blocks
    __shared__ int sm[32];
    __shared__ int s_total;
    __shared__ int s_base;

    int b = blockIdx.x;
    int i = b * SCAN_CHUNK + threadIdx.x;
    int v = (i < N_NODES) ? g_deg[i] : 0;
    int ex = block_scan_excl(v, sm);
    if (threadIdx.x == SCAN_CHUNK - 1) s_total = ex + v;
    __syncthreads();
    int total = s_total;

    if (threadIdx.x < 32) {
        int lane = threadIdx.x;
        int base = 0;
        if (b == 0) {
            if (lane == 0) {
                __threadfence();
                atomicExch(&g_pack[0], (2ull << 32) | (unsigned)total);
            }
        } else {
            if (lane == 0) {
                __threadfence();
                atomicExch(&g_pack[b], (1ull << 32) | (unsigned)total);
            }
            int p = b - 1;
            bool done = false;
            while (!done) {
                int idx = p - lane;
                u64 w = 0;
                if (idx >= 0) {
                    do { w = atomicAdd(&g_pack[idx], 0ull); } while ((w >> 32) == 0);
                }
                int f = (int)(w >> 32);
                int val = (int)(w & 0xffffffffu);
                unsigned pm = __ballot_sync(0xffffffffu, idx >= 0 && f == 2);
                int cut;
                if (pm) { cut = __ffs(pm) - 1; done = true; }
                else    { cut = (p >= 31) ? 31 : p; }
                int contrib = (lane <= cut && idx >= 0) ? val : 0;
#pragma unroll
                for (int d = 16; d > 0; d >>= 1)
                    contrib += __shfl_xor_sync(0xffffffffu, contrib, d);
                base += contrib;
                p -= 32;
                if (p < 0) done = true;
            }
            if (lane == 0) {
                __threadfence();
                atomicExch(&g_pack[b], (2ull << 32) | (unsigned)(base + total));
                s_base = base;
            }
        }
        if (lane == 0 && b == 0) s_base = 0;
    }
    __syncthreads();
    int base = s_base;
    if (i < N_NODES) {
        g_off[i] = base + ex;
        g_cur[i] = base + ex;
    }
    if (b == NCHUNK - 1 && threadIdx.x == 0) g_off[N_NODES] = N_EDGES;
}

// ============ K4: CSR fill (int4 vectorized) ==============================

__global__ void k_fill(const int* __restrict__ ei) {
    int t = blockIdx.x * blockDim.x + threadIdx.x;
    if (t < N_EDGES / 4) {
        int4 s = ((const int4*)ei)[t];
        int4 d = ((const int4*)(ei + N_EDGES))[t];
        g_csr_src[atomicAdd(&g_cur[d.x], 1)] = s.x;
        g_csr_src[atomicAdd(&g_cur[d.y], 1)] = s.y;
        g_csr_src[atomicAdd(&g_cur[d.z], 1)] = s.z;
        g_csr_src[atomicAdd(&g_cur[d.w], 1)] = s.w;
    }
}

// ============ K5: fused SpMM1 + relu + GEMM2 ==============================
// warp per node: gather-sum h1 neighbors (float2/lane), relu -> smem,
// then lanes 0..19 compute 2 output cols each of h2 = a1 @ W2 (packed FMA2).

__global__ __launch_bounds__(256) void k_spmm1_gemm2(const float* __restrict__ W2) {
    __shared__ float W2s[HID_C * OUT_C];        // 10.25 KB
    __shared__ float a1s[8][HID_C];             // 2 KB
    for (int i = threadIdx.x; i < HID_C * OUT_C; i += blockDim.x) W2s[i] = W2[i];
    __syncthreads();

    int w = threadIdx.x >> 5;
    int lane = threadIdx.x & 31;
    int gw = blockIdx.x * 8 + w;
    if (gw >= N_NODES) return;

    int beg = g_off[gw], end = g_off[gw + 1];
    const float2* h1v = (const float2*)g_h1;

    float2 acc = make_float2(0.f, 0.f);
#pragma unroll 4
    for (int idx = beg; idx < end; idx++) {
        int s = __ldg(&g_csr_src[idx]);              // uniform broadcast load
        float2 hv = __ldg(&h1v[(size_t)s * (HID_C / 2) + lane]);
        acc.x += hv.x;
        acc.y += hv.y;
    }
    ((float2*)a1s[w])[lane] = make_float2(fmaxf(acc.x, 0.f), fmaxf(acc.y, 0.f));
    __syncwarp();

    if (lane < OUT_C / 2) {
        u64 o2 = 0ull;
        const float* a = a1s[w];
        const float* wp = W2s + 2 * lane;
#pragma unroll
        for (int k = 0; k < HID_C; k++) {
            u64 a2 = pack2(a[k]);                    // smem broadcast
            fma2(o2, a2, *(const u64*)(wp + k * OUT_C));
        }
        ((u64*)g_h2)[(size_t)gw * (OUT_C / 2) + lane] = o2;
    }
}

// ============ K6: SpMM2 + log_softmax =====================================

__global__ __launch_bounds__(256) void k_spmm2_lsm(float* __restrict__ out) {
    int w = threadIdx.x >> 5;
    int lane = threadIdx.x & 31;
    int gw = blockIdx.x * 8 + w;
    if (gw >= N_NODES) return;

    int beg = g_off[gw], end = g_off[gw + 1];
    const float2* h2v = (const float2*)g_h2;
    bool active = lane < (OUT_C / 2);
    int cl = active ? lane : 0;                      // clamp so inactive lanes load safely

    float2 acc = make_float2(0.f, 0.f);
#pragma unroll 4
    for (int idx = beg; idx < end; idx++) {
        int s = __ldg(&g_csr_src[idx]);
        float2 hv = __ldg(&h2v[(size_t)s * (OUT_C / 2) + cl]);
        acc.x += hv.x;
        acc.y += hv.y;
    }

    float m = active ? fmaxf(acc.x, acc.y) : -INFINITY;
#pragma unroll
    for (int d = 16; d > 0; d >>= 1) m = fmaxf(m, __shfl_xor_sync(0xffffffffu, m, d));
    float sum = active ? (expf(acc.x - m) + expf(acc.y - m)) : 0.f;
#pragma unroll
    for (int d = 16; d > 0; d >>= 1) sum += __shfl_xor_sync(0xffffffffu, sum, d);
    float lse = logf(sum);
    if (active) {
        ((float2*)out)[(size_t)gw * (OUT_C / 2) + lane] =
            make_float2(acc.x - m - lse, acc.y - m - lse);
    }
}

// ---------------- launch ---------------------------------------------------

extern "C" void kernel_launch(void* const* d_in, const int* in_sizes, int n_in,
                              void* d_out, int out_size) {
    const float* x  = (const float*)d_in[0];     // [80000,128]
    const int*   ei = (const int*)d_in[1];       // [2,1280000]
    const float* W1 = (const float*)d_in[2];     // [128,64]
    const float* W2 = (const float*)d_in[3];     // [64,40]
    float* out = (float*)d_out;                  // [80000,40]

    const int TB = 256;

    k_gemm1_zero<<<(N_NODES + TB - 1) / TB, TB>>>(x, W1);
    k_hist<<<(N_EDGES / 4 + TB - 1) / TB, TB>>>(ei);
    k_scan<<<NCHUNK, SCAN_CHUNK>>>();
    k_fill<<<(N_EDGES / 4 + TB - 1) / TB, TB>>>(ei);
    k_spmm1_gemm2<<<(N_NODES + 7) / 8, TB>>>(W2);
    k_spmm2_lsm<<<(N_NODES + 7) / 8, TB>>>(out);
}

// round 5
// speedup vs baseline: 1.2124x; 1.1871x over previous
#include <cuda_runtime.h>
#include <math.h>

#define N_NODES 80000
#define N_EDGES 1280000
#define IN_C    128
#define HID_C   64
#define OUT_C   40

#define SCAN_CHUNK 1024
#define NCHUNK ((N_NODES + SCAN_CHUNK - 1) / SCAN_CHUNK)   // 79

typedef unsigned long long u64;

// ---------------- static device scratch (no allocations allowed) ----------
__device__ float g_h1[N_NODES * HID_C];     // x @ W1
__device__ float g_a1[N_NODES * HID_C];     // relu(agg(h1))
__device__ float g_h2[N_NODES * OUT_C];     // a1 @ W2
__device__ int   g_deg[N_NODES];
__device__ int   g_off[N_NODES + 1];
__device__ int   g_cur[N_NODES];
__device__ int   g_csr_src[N_EDGES];
__device__ u64   g_pack[NCHUNK];            // lookback: (flag<<32)|value

// ============ branch A: CSR build =========================================

__global__ void k_zero() {
    int i = blockIdx.x * blockDim.x + threadIdx.x;
    if (i < N_NODES) g_deg[i] = 0;
    if (i < NCHUNK)  g_pack[i] = 0ull;
}

__global__ void k_hist(const int* __restrict__ ei) {
    int t = blockIdx.x * blockDim.x + threadIdx.x;
    if (t < N_EDGES / 4) {
        int4 d = ((const int4*)(ei + N_EDGES))[t];
        atomicAdd(&g_deg[d.x], 1);
        atomicAdd(&g_deg[d.y], 1);
        atomicAdd(&g_deg[d.z], 1);
        atomicAdd(&g_deg[d.w], 1);
    }
}

__device__ __forceinline__ int block_scan_excl(int v, int* smem32) {
    int lane = threadIdx.x & 31;
    int wid  = threadIdx.x >> 5;
    int nw   = blockDim.x >> 5;
    int s = v;
#pragma unroll
    for (int d = 1; d < 32; d <<= 1) {
        int t = __shfl_up_sync(0xffffffffu, s, d);
        if (lane >= d) s += t;
    }
    if (lane == 31) smem32[wid] = s;
    __syncthreads();
    if (wid == 0) {
        int ws = (lane < nw) ? smem32[lane] : 0;
        int ss = ws;
#pragma unroll
        for (int d = 1; d < 32; d <<= 1) {
            int t = __shfl_up_sync(0xffffffffu, ss, d);
            if (lane >= d) ss += t;
        }
        smem32[lane] = ss - ws;
    }
    __syncthreads();
    return smem32[wid] + (s - v);
}

__global__ __launch_bounds__(SCAN_CHUNK) void k_scan() {   // NCHUNK blocks
    __shared__ int sm[32];
    __shared__ int s_total;
    __shared__ int s_base;

    int b = blockIdx.x;
    int i = b * SCAN_CHUNK + threadIdx.x;
    int v = (i < N_NODES) ? g_deg[i] : 0;
    int ex = block_scan_excl(v, sm);
    if (threadIdx.x == SCAN_CHUNK - 1) s_total = ex + v;
    __syncthreads();
    int total = s_total;

    if (threadIdx.x < 32) {
        int lane = threadIdx.x;
        int base = 0;
        if (b == 0) {
            if (lane == 0) {
                __threadfence();
                atomicExch(&g_pack[0], (2ull << 32) | (unsigned)total);
            }
        } else {
            if (lane == 0) {
                __threadfence();
                atomicExch(&g_pack[b], (1ull << 32) | (unsigned)total);
            }
            int p = b - 1;
            bool done = false;
            while (!done) {
                int idx = p - lane;
                u64 w = 0;
                if (idx >= 0) {
                    do { w = atomicAdd(&g_pack[idx], 0ull); } while ((w >> 32) == 0);
                }
                int f = (int)(w >> 32);
                int val = (int)(w & 0xffffffffu);
                unsigned pm = __ballot_sync(0xffffffffu, idx >= 0 && f == 2);
                int cut;
                if (pm) { cut = __ffs(pm) - 1; done = true; }
                else    { cut = (p >= 31) ? 31 : p; }
                int contrib = (lane <= cut && idx >= 0) ? val : 0;
#pragma unroll
                for (int d = 16; d > 0; d >>= 1)
                    contrib += __shfl_xor_sync(0xffffffffu, contrib, d);
                base += contrib;
                p -= 32;
                if (p < 0) done = true;
            }
            if (lane == 0) {
                __threadfence();
                atomicExch(&g_pack[b], (2ull << 32) | (unsigned)(base + total));
                s_base = base;
            }
        }
        if (lane == 0 && b == 0) s_base = 0;
    }
    __syncthreads();
    int base = s_base;
    if (i < N_NODES) {
        g_off[i] = base + ex;
        g_cur[i] = base + ex;
    }
    if (b == NCHUNK - 1 && threadIdx.x == 0) g_off[N_NODES] = N_EDGES;
}

__global__ void k_fill(const int* __restrict__ ei) {
    int t = blockIdx.x * blockDim.x + threadIdx.x;
    if (t < N_EDGES / 4) {
        int4 s = ((const int4*)ei)[t];
        int4 d = ((const int4*)(ei + N_EDGES))[t];
        g_csr_src[atomicAdd(&g_cur[d.x], 1)] = s.x;
        g_csr_src[atomicAdd(&g_cur[d.y], 1)] = s.y;
        g_csr_src[atomicAdd(&g_cur[d.z], 1)] = s.z;
        g_csr_src[atomicAdd(&g_cur[d.w], 1)] = s.w;
    }
}

// ============ branch B: GEMM1 (h1 = x @ W1) — R1-proven float4 form =======

__global__ __launch_bounds__(256) void k_gemm1(const float* __restrict__ x,
                                               const float* __restrict__ W1) {
    __shared__ float Ws[IN_C * HID_C];   // 32 KB
    for (int i = threadIdx.x; i < IN_C * HID_C; i += blockDim.x) Ws[i] = W1[i];
    __syncthreads();

    int v = blockIdx.x * blockDim.x + threadIdx.x;
    if (v >= N_NODES) return;

    float acc[HID_C];
#pragma unroll
    for (int j = 0; j < HID_C; j++) acc[j] = 0.f;

    const float4* xr = (const float4*)(x + (size_t)v * IN_C);
#pragma unroll 2
    for (int k4 = 0; k4 < IN_C / 4; k4++) {
        float4 xv = xr[k4];
        int kb = k4 * 4;
#pragma unroll
        for (int c = 0; c < 4; c++) {
            float xc = (c == 0) ? xv.x : (c == 1) ? xv.y : (c == 2) ? xv.z : xv.w;
            const float4* wr = (const float4*)(Ws + (kb + c) * HID_C);
#pragma unroll
            for (int j4 = 0; j4 < HID_C / 4; j4++) {
                float4 w = wr[j4];
                acc[4 * j4 + 0] += xc * w.x;
                acc[4 * j4 + 1] += xc * w.y;
                acc[4 * j4 + 2] += xc * w.z;
                acc[4 * j4 + 3] += xc * w.w;
            }
        }
    }
    float4* o = (float4*)(g_h1 + (size_t)v * HID_C);
#pragma unroll
    for (int j4 = 0; j4 < HID_C / 4; j4++)
        o[j4] = make_float4(acc[4*j4], acc[4*j4+1], acc[4*j4+2], acc[4*j4+3]);
}

// ============ SpMM1 + relu (R1-proven form) ===============================

__global__ void k_spmm1() {
    int gw = (blockIdx.x * blockDim.x + threadIdx.x) >> 5;
    if (gw >= N_NODES) return;
    int lane = threadIdx.x & 31;
    int beg = g_off[gw], end = g_off[gw + 1];

    const float2* h1v = (const float2*)g_h1;
    float2 acc = make_float2(0.f, 0.f);
#pragma unroll 4
    for (int idx = beg; idx < end; idx++) {
        int s = __ldg(&g_csr_src[idx]);          // uniform across warp
        float2 hv = __ldg(&h1v[(size_t)s * (HID_C / 2) + lane]);
        acc.x += hv.x;
        acc.y += hv.y;
    }
    ((float2*)g_a1)[(size_t)gw * (HID_C / 2) + lane] =
        make_float2(fmaxf(acc.x, 0.f), fmaxf(acc.y, 0.f));
}

// ============ GEMM2 (R1-proven float4 form) ===============================

__global__ __launch_bounds__(256) void k_gemm2(const float* __restrict__ W2) {
    __shared__ float Ws[HID_C * OUT_C];  // 10.25 KB
    for (int i = threadIdx.x; i < HID_C * OUT_C; i += blockDim.x) Ws[i] = W2[i];
    __syncthreads();

    int v = blockIdx.x * blockDim.x + threadIdx.x;
    if (v >= N_NODES) return;

    float acc[OUT_C];
#pragma unroll
    for (int j = 0; j < OUT_C; j++) acc[j] = 0.f;

    const float4* ar = (const float4*)(g_a1 + (size_t)v * HID_C);
#pragma unroll 2
    for (int k4 = 0; k4 < HID_C / 4; k4++) {
        float4 av = ar[k4];
        int kb = k4 * 4;
#pragma unroll
        for (int c = 0; c < 4; c++) {
            float ac = (c == 0) ? av.x : (c == 1) ? av.y : (c == 2) ? av.z : av.w;
            const float4* wr = (const float4*)(Ws + (kb + c) * OUT_C);
#pragma unroll
            for (int j4 = 0; j4 < OUT_C / 4; j4++) {
                float4 w = wr[j4];
                acc[4 * j4 + 0] += ac * w.x;
                acc[4 * j4 + 1] += ac * w.y;
                acc[4 * j4 + 2] += ac * w.z;
                acc[4 * j4 + 3] += ac * w.w;
            }
        }
    }
    float4* o = (float4*)(g_h2 + (size_t)v * OUT_C);
#pragma unroll
    for (int j4 = 0; j4 < OUT_C / 4; j4++)
        o[j4] = make_float4(acc[4*j4], acc[4*j4+1], acc[4*j4+2], acc[4*j4+3]);
}

// ============ SpMM2 + log_softmax (R1-proven form) ========================

__global__ void k_spmm2_lsm(float* __restrict__ out) {
    int gw = (blockIdx.x * blockDim.x + threadIdx.x) >> 5;
    if (gw >= N_NODES) return;
    int lane = threadIdx.x & 31;
    int beg = g_off[gw], end = g_off[gw + 1];

    const float2* h2v = (const float2*)g_h2;
    bool active = lane < (OUT_C / 2);
    int cl = active ? lane : 0;

    float2 acc = make_float2(0.f, 0.f);
#pragma unroll 4
    for (int idx = beg; idx < end; idx++) {
        int s = __ldg(&g_csr_src[idx]);
        float2 hv = __ldg(&h2v[(size_t)s * (OUT_C / 2) + cl]);
        acc.x += hv.x;
        acc.y += hv.y;
    }

    float m = active ? fmaxf(acc.x, acc.y) : -INFINITY;
#pragma unroll
    for (int d = 16; d > 0; d >>= 1) m = fmaxf(m, __shfl_xor_sync(0xffffffffu, m, d));
    float sum = active ? (expf(acc.x - m) + expf(acc.y - m)) : 0.f;
#pragma unroll
    for (int d = 16; d > 0; d >>= 1) sum += __shfl_xor_sync(0xffffffffu, sum, d);
    float lse = logf(sum);
    if (active) {
        ((float2*)out)[(size_t)gw * (OUT_C / 2) + lane] =
            make_float2(acc.x - m - lse, acc.y - m - lse);
    }
}

// ---------------- launch: forked graph ------------------------------------
// branch A (stream 0):  zero -> hist -> scan -> fill      (~40 us, atomic-bound)
// branch B (side strm): gemm1                             (~22 us, fma-bound)
// join -> spmm1 -> gemm2 -> spmm2_lsm

extern "C" void kernel_launch(void* const* d_in, const int* in_sizes, int n_in,
                              void* d_out, int out_size) {
    const float* x  = (const float*)d_in[0];     // [80000,128]
    const int*   ei = (const int*)d_in[1];       // [2,1280000]
    const float* W1 = (const float*)d_in[2];     // [128,64]
    const float* W2 = (const float*)d_in[3];     // [64,40]
    float* out = (float*)d_out;                  // [80000,40]

    const int TB = 256;

    // fresh host-side objects each call (never device memory; not freed so no
    // capture-lifetime issues; kernel_launch runs only a handful of times)
    cudaStream_t sB;
    cudaEvent_t eFork, eJoin;
    cudaStreamCreateWithFlags(&sB, cudaStreamNonBlocking);
    cudaEventCreateWithFlags(&eFork, cudaEventDisableTiming);
    cudaEventCreateWithFlags(&eJoin, cudaEventDisableTiming);

    // fork
    cudaEventRecord(eFork, 0);
    cudaStreamWaitEvent(sB, eFork, 0);

    // branch B: GEMM1 on side stream
    k_gemm1<<<(N_NODES + TB - 1) / TB, TB, 0, sB>>>(x, W1);
    cudaEventRecord(eJoin, sB);

    // branch A: CSR build on main stream
    k_zero<<<(N_NODES + TB - 1) / TB, TB>>>();
    k_hist<<<(N_EDGES / 4 + TB - 1) / TB, TB>>>(ei);
    k_scan<<<NCHUNK, SCAN_CHUNK>>>();
    k_fill<<<(N_EDGES / 4 + TB - 1) / TB, TB>>>(ei);

    // join: spmm1 needs both h1 and CSR
    cudaStreamWaitEvent(0, eJoin, 0);

    k_spmm1<<<(N_NODES * 32 + TB - 1) / TB, TB>>>();
    k_gemm2<<<(N_NODES + TB - 1) / TB, TB>>>(W2);
    k_spmm2_lsm<<<(N_NODES * 32 + TB - 1) / TB, TB>>>(out);
}

// round 9
// speedup vs baseline: 1.3200x; 1.0887x over previous
#include <cuda_runtime.h>
#include <cuda_fp16.h>
#include <math.h>

#define N_NODES 80000
#define N_EDGES 1280000
#define IN_C    128
#define HID_C   64
#define OUT_C   40

#define SCAN_CHUNK 1024
#define NCHUNK ((N_NODES + SCAN_CHUNK - 1) / SCAN_CHUNK)   // 79

typedef unsigned long long u64;

// bit-cast helper (register reinterpretation, no instruction)
__device__ __forceinline__ unsigned h2_bits(__half2 h) {
    return *reinterpret_cast<unsigned*>(&h);
}

// ---------------- static device scratch (no allocations allowed) ----------
__device__ __half g_h1[N_NODES * HID_C];    // x @ W1          (fp16, gathered)
__device__ float  g_a1[N_NODES * HID_C];    // relu(agg(h1))   (fp32, dense)
__device__ __half g_h2[N_NODES * OUT_C];    // a1 @ W2         (fp16, gathered)
__device__ int    g_deg[N_NODES];
__device__ int    g_off[N_NODES + 1];
__device__ int    g_cur[N_NODES];
__device__ int    g_csr_src[N_EDGES];
__device__ u64    g_pack[NCHUNK];           // lookback: (flag<<32)|value

// ============ branch A: CSR build =========================================

__global__ void k_zero() {
    int i = blockIdx.x * blockDim.x + threadIdx.x;
    if (i < N_NODES) g_deg[i] = 0;
    if (i < NCHUNK)  g_pack[i] = 0ull;
}

__global__ void k_hist(const int* __restrict__ ei) {
    int t = blockIdx.x * blockDim.x + threadIdx.x;
    if (t < N_EDGES / 4) {
        int4 d = ((const int4*)(ei + N_EDGES))[t];
        atomicAdd(&g_deg[d.x], 1);
        atomicAdd(&g_deg[d.y], 1);
        atomicAdd(&g_deg[d.z], 1);
        atomicAdd(&g_deg[d.w], 1);
    }
}

__device__ __forceinline__ int block_scan_excl(int v, int* smem32) {
    int lane = threadIdx.x & 31;
    int wid  = threadIdx.x >> 5;
    int nw   = blockDim.x >> 5;
    int s = v;
#pragma unroll
    for (int d = 1; d < 32; d <<= 1) {
        int t = __shfl_up_sync(0xffffffffu, s, d);
        if (lane >= d) s += t;
    }
    if (lane == 31) smem32[wid] = s;
    __syncthreads();
    if (wid == 0) {
        int ws = (lane < nw) ? smem32[lane] : 0;
        int ss = ws;
#pragma unroll
        for (int d = 1; d < 32; d <<= 1) {
            int t = __shfl_up_sync(0xffffffffu, ss, d);
            if (lane >= d) ss += t;
        }
        smem32[lane] = ss - ws;
    }
    __syncthreads();
    return smem32[wid] + (s - v);
}

__global__ __launch_bounds__(SCAN_CHUNK) void k_scan() {   // NCHUNK blocks
    __shared__ int sm[32];
    __shared__ int s_total;
    __shared__ int s_base;

    int b = blockIdx.x;
    int i = b * SCAN_CHUNK + threadIdx.x;
    int v = (i < N_NODES) ? g_deg[i] : 0;
    int ex = block_scan_excl(v, sm);
    if (threadIdx.x == SCAN_CHUNK - 1) s_total = ex + v;
    __syncthreads();
    int total = s_total;

    if (threadIdx.x < 32) {
        int lane = threadIdx.x;
        int base = 0;
        if (b == 0) {
            if (lane == 0) {
                __threadfence();
                atomicExch(&g_pack[0], (2ull << 32) | (unsigned)total);
            }
        } else {
            if (lane == 0) {
                __threadfence();
                atomicExch(&g_pack[b], (1ull << 32) | (unsigned)total);
            }
            int p = b - 1;
            bool done = false;
            while (!done) {
                int idx = p - lane;
                u64 w = 0;
                if (idx >= 0) {
                    do { w = atomicAdd(&g_pack[idx], 0ull); } while ((w >> 32) == 0);
                }
                int f = (int)(w >> 32);
                int val = (int)(w & 0xffffffffu);
                unsigned pm = __ballot_sync(0xffffffffu, idx >= 0 && f == 2);
                int cut;
                if (pm) { cut = __ffs(pm) - 1; done = true; }
                else    { cut = (p >= 31) ? 31 : p; }
                int contrib = (lane <= cut && idx >= 0) ? val : 0;
#pragma unroll
                for (int d = 16; d > 0; d >>= 1)
                    contrib += __shfl_xor_sync(0xffffffffu, contrib, d);
                base += contrib;
                p -= 32;
                if (p < 0) done = true;
            }
            if (lane == 0) {
                __threadfence();
                atomicExch(&g_pack[b], (2ull << 32) | (unsigned)(base + total));
                s_base = base;
            }
        }
        if (lane == 0 && b == 0) s_base = 0;
    }
    __syncthreads();
    int base = s_base;
    if (i < N_NODES) {
        g_off[i] = base + ex;
        g_cur[i] = base + ex;
    }
    if (b == NCHUNK - 1 && threadIdx.x == 0) g_off[N_NODES] = N_EDGES;
}

__global__ void k_fill(const int* __restrict__ ei) {
    int t = blockIdx.x * blockDim.x + threadIdx.x;
    if (t < N_EDGES / 4) {
        int4 s = ((const int4*)ei)[t];
        int4 d = ((const int4*)(ei + N_EDGES))[t];
        g_csr_src[atomicAdd(&g_cur[d.x], 1)] = s.x;
        g_csr_src[atomicAdd(&g_cur[d.y], 1)] = s.y;
        g_csr_src[atomicAdd(&g_cur[d.z], 1)] = s.z;
        g_csr_src[atomicAdd(&g_cur[d.w], 1)] = s.w;
    }
}

// ============ branch B: GEMM1 (h1 = x @ W1, fp32 math, fp16 store) ========

__global__ __launch_bounds__(256) void k_gemm1(const float* __restrict__ x,
                                               const float* __restrict__ W1) {
    __shared__ float Ws[IN_C * HID_C];   // 32 KB
    for (int i = threadIdx.x; i < IN_C * HID_C; i += blockDim.x) Ws[i] = W1[i];
    __syncthreads();

    int v = blockIdx.x * blockDim.x + threadIdx.x;
    if (v >= N_NODES) return;

    float acc[HID_C];
#pragma unroll
    for (int j = 0; j < HID_C; j++) acc[j] = 0.f;

    const float4* xr = (const float4*)(x + (size_t)v * IN_C);
#pragma unroll 2
    for (int k4 = 0; k4 < IN_C / 4; k4++) {
        float4 xv = xr[k4];
        int kb = k4 * 4;
#pragma unroll
        for (int c = 0; c < 4; c++) {
            float xc = (c == 0) ? xv.x : (c == 1) ? xv.y : (c == 2) ? xv.z : xv.w;
            const float4* wr = (const float4*)(Ws + (kb + c) * HID_C);
#pragma unroll
            for (int j4 = 0; j4 < HID_C / 4; j4++) {
                float4 w = wr[j4];
                acc[4 * j4 + 0] += xc * w.x;
                acc[4 * j4 + 1] += xc * w.y;
                acc[4 * j4 + 2] += xc * w.z;
                acc[4 * j4 + 3] += xc * w.w;
            }
        }
    }
    // pack 64 floats -> 32 half2 -> 8 x uint4 stores (row = 128 B)
    uint4* o = (uint4*)(g_h1 + (size_t)v * HID_C);
#pragma unroll
    for (int j8 = 0; j8 < HID_C / 8; j8++) {
        __half2 p0 = __float22half2_rn(make_float2(acc[8*j8+0], acc[8*j8+1]));
        __half2 p1 = __float22half2_rn(make_float2(acc[8*j8+2], acc[8*j8+3]));
        __half2 p2 = __float22half2_rn(make_float2(acc[8*j8+4], acc[8*j8+5]));
        __half2 p3 = __float22half2_rn(make_float2(acc[8*j8+6], acc[8*j8+7]));
        o[j8] = make_uint4(h2_bits(p0), h2_bits(p1), h2_bits(p2), h2_bits(p3));
    }
}

// ============ SpMM1 + relu: a1 = relu(agg(h1)), fp16 gather, fp32 acc =====

__global__ void k_spmm1() {
    int gw = (blockIdx.x * blockDim.x + threadIdx.x) >> 5;
    if (gw >= N_NODES) return;
    int lane = threadIdx.x & 31;
    int beg = g_off[gw], end = g_off[gw + 1];

    const __half2* h1v = (const __half2*)g_h1;   // 32 half2 per row
    float2 acc = make_float2(0.f, 0.f);
#pragma unroll 4
    for (int idx = beg; idx < end; idx++) {
        int s = __ldg(&g_csr_src[idx]);          // uniform across warp
        __half2 hv = __ldg(&h1v[(size_t)s * (HID_C / 2) + lane]);
        float2 f = __half22float2(hv);
        acc.x += f.x;
        acc.y += f.y;
    }
    ((float2*)g_a1)[(size_t)gw * (HID_C / 2) + lane] =
        make_float2(fmaxf(acc.x, 0.f), fmaxf(acc.y, 0.f));
}

// ============ GEMM2: h2 = a1 @ W2 (fp32 math, fp16 store) =================

__global__ __launch_bounds__(256) void k_gemm2(const float* __restrict__ W2) {
    __shared__ float Ws[HID_C * OUT_C];  // 10.25 KB
    for (int i = threadIdx.x; i < HID_C * OUT_C; i += blockDim.x) Ws[i] = W2[i];
    __syncthreads();

    int v = blockIdx.x * blockDim.x + threadIdx.x;
    if (v >= N_NODES) return;

    float acc[OUT_C];
#pragma unroll
    for (int j = 0; j < OUT_C; j++) acc[j] = 0.f;

    const float4* ar = (const float4*)(g_a1 + (size_t)v * HID_C);
#pragma unroll 2
    for (int k4 = 0; k4 < HID_C / 4; k4++) {
        float4 av = ar[k4];
        int kb = k4 * 4;
#pragma unroll
        for (int c = 0; c < 4; c++) {
            float ac = (c == 0) ? av.x : (c == 1) ? av.y : (c == 2) ? av.z : av.w;
            const float4* wr = (const float4*)(Ws + (kb + c) * OUT_C);
#pragma unroll
            for (int j4 = 0; j4 < OUT_C / 4; j4++) {
                float4 w = wr[j4];
                acc[4 * j4 + 0] += ac * w.x;
                acc[4 * j4 + 1] += ac * w.y;
                acc[4 * j4 + 2] += ac * w.z;
                acc[4 * j4 + 3] += ac * w.w;
            }
        }
    }
    // pack 40 floats -> 20 half2 = 20 words -> 5 x uint4 stores (row = 80 B,
    // v*80 is 16B-aligned)
    unsigned up[OUT_C / 2];                      // 20 words (R7 bug: was [10])
#pragma unroll
    for (int j = 0; j < OUT_C / 2; j++) {
        __half2 h = __float22half2_rn(make_float2(acc[2*j], acc[2*j+1]));
        up[j] = h2_bits(h);
    }
    uint4* row = (uint4*)(g_h2 + (size_t)v * OUT_C);
#pragma unroll
    for (int q = 0; q < 5; q++)
        row[q] = make_uint4(up[4*q], up[4*q+1], up[4*q+2], up[4*q+3]);
}

// ============ SpMM2 + log_softmax (fp16 gather, fp32 acc) =================

__global__ void k_spmm2_lsm(float* __restrict__ out) {
    int gw = (blockIdx.x * blockDim.x + threadIdx.x) >> 5;
    if (gw >= N_NODES) return;
    int lane = threadIdx.x & 31;
    int beg = g_off[gw], end = g_off[gw + 1];

    const __half2* h2v = (const __half2*)g_h2;   // 20 half2 per row
    bool active = lane < (OUT_C / 2);
    int cl = active ? lane : 0;

    float2 acc = make_float2(0.f, 0.f);
#pragma unroll 4
    for (int idx = beg; idx < end; idx++) {
        int s = __ldg(&g_csr_src[idx]);
        __half2 hv = __ldg(&h2v[(size_t)s * (OUT_C / 2) + cl]);
        float2 f = __half22float2(hv);
        acc.x += f.x;
        acc.y += f.y;
    }

    float m = active ? fmaxf(acc.x, acc.y) : -INFINITY;
#pragma unroll
    for (int d = 16; d > 0; d >>= 1) m = fmaxf(m, __shfl_xor_sync(0xffffffffu, m, d));
    float sum = active ? (expf(acc.x - m) + expf(acc.y - m)) : 0.f;
#pragma unroll
    for (int d = 16; d > 0; d >>= 1) sum += __shfl_xor_sync(0xffffffffu, sum, d);
    float lse = logf(sum);
    if (active) {
        ((float2*)out)[(size_t)gw * (OUT_C / 2) + lane] =
            make_float2(acc.x - m - lse, acc.y - m - lse);
    }
}

// ---------------- launch: forked graph ------------------------------------
// branch A (stream 0):  zero -> hist -> scan -> fill      (~42 us, atomic-bound)
// branch B (side strm): gemm1                             (~22 us, fma-bound)
// join -> spmm1 -> gemm2 -> spmm2_lsm

extern "C" void kernel_launch(void* const* d_in, const int* in_sizes, int n_in,
                              void* d_out, int out_size) {
    const float* x  = (const float*)d_in[0];     // [80000,128]
    const int*   ei = (const int*)d_in[1];       // [2,1280000]
    const float* W1 = (const float*)d_in[2];     // [128,64]
    const float* W2 = (const float*)d_in[3];     // [64,40]
    float* out = (float*)d_out;                  // [80000,40]

    const int TB = 256;

    cudaStream_t sB;
    cudaEvent_t eFork, eJoin;
    cudaStreamCreateWithFlags(&sB, cudaStreamNonBlocking);
    cudaEventCreateWithFlags(&eFork, cudaEventDisableTiming);
    cudaEventCreateWithFlags(&eJoin, cudaEventDisableTiming);

    // fork
    cudaEventRecord(eFork, 0);
    cudaStreamWaitEvent(sB, eFork, 0);

    // branch B: GEMM1 on side stream
    k_gemm1<<<(N_NODES + TB - 1) / TB, TB, 0, sB>>>(x, W1);
    cudaEventRecord(eJoin, sB);

    // branch A: CSR build on main stream
    k_zero<<<(N_NODES + TB - 1) / TB, TB>>>();
    k_hist<<<(N_EDGES / 4 + TB - 1) / TB, TB>>>(ei);
    k_scan<<<NCHUNK, SCAN_CHUNK>>>();
    k_fill<<<(N_EDGES / 4 + TB - 1) / TB, TB>>>(ei);

    // join: spmm1 needs both h1 and CSR
    cudaStreamWaitEvent(0, eJoin, 0);

    k_spmm1<<<(N_NODES * 32 + TB - 1) / TB, TB>>>();
    k_gemm2<<<(N_NODES + TB - 1) / TB, TB>>>(W2);
    k_spmm2_lsm<<<(N_NODES * 32 + TB - 1) / TB, TB>>>(out);
}